// round 1
// baseline (speedup 1.0000x reference)
#include <cuda_runtime.h>

#define BB 2
#define HH 160
#define WW 160
#define NPTS 2048
#define HW (HH*WW)
#define TOTAL (BB*HW)

// Scratch: per-pixel target indicator (0/1). Device global per allocation rules.
__device__ unsigned char g_T[TOTAL];

__global__ void k_zero(float* out) {
    int i = blockIdx.x * blockDim.x + threadIdx.x;
    if (i < TOTAL) g_T[i] = 0;
    if (i == 0) *out = 0.0f;
}

// Each point can mark at most one pixel center (grid pitch 16 > 2*radius 8).
// Check the 2x2 floor-neighborhood to be robust to float rounding at the
// midpoint; exact test matches reference: sqrtf(d2) < 8.0f.
__global__ void k_scatter(const float* __restrict__ pts, const int* __restrict__ downp) {
    int t = blockIdx.x * blockDim.x + threadIdx.x;
    if (t >= BB * NPTS) return;
    int b = t / NPTS;
    float down = downp ? (float)(*downp) : 16.0f;
    float half = (down - 1.0f) * 0.5f;
    float inv  = 1.0f / down;
    float p0 = pts[2 * t + 0];   // pairs with row coord (y)
    float p1 = pts[2 * t + 1];   // pairs with col coord (x)
    int i0 = (int)floorf((p0 - half) * inv);
    int j0 = (int)floorf((p1 - half) * inv);
    #pragma unroll
    for (int di = 0; di < 2; di++) {
        int i = i0 + di;
        if (i < 0 || i >= HH) continue;
        float dy = fmaf((float)i, down, half) - p0;
        #pragma unroll
        for (int dj = 0; dj < 2; dj++) {
            int j = j0 + dj;
            if (j < 0 || j >= WW) continue;
            float dx = fmaf((float)j, down, half) - p1;
            if (sqrtf(dy * dy + dx * dx) < 8.0f) {
                g_T[b * HW + i * WW + j] = 1;  // same-value racing stores are fine
            }
        }
    }
}

__global__ void k_loss(const float* __restrict__ dens, float* __restrict__ out) {
    int i = blockIdx.x * blockDim.x + threadIdx.x;
    float v = 0.0f;
    if (i < TOTAL) {
        float A = dens[i];
        float t = (float)g_T[i];
        // stable BCE-with-logits: max(A,0) - A*t + log1p(exp(-|A|))
        float elem = fmaxf(A, 0.0f) - A * t + log1pf(__expf(-fabsf(A)));
        v = (t + 1.0f) * elem;
    }
    // intra-warp reduce
    #pragma unroll
    for (int o = 16; o > 0; o >>= 1) v += __shfl_down_sync(0xffffffffu, v, o);
    __shared__ float s[8];
    int lane = threadIdx.x & 31;
    int w    = threadIdx.x >> 5;
    if (lane == 0) s[w] = v;
    __syncthreads();
    if (w == 0) {
        v = (lane < (int)(blockDim.x >> 5)) ? s[lane] : 0.0f;
        #pragma unroll
        for (int o = 4; o > 0; o >>= 1) v += __shfl_down_sync(0xffu, v, o);
        if (lane == 0) atomicAdd(out, v * (1.0f / (float)TOTAL));
    }
}

extern "C" void kernel_launch(void* const* d_in, const int* in_sizes, int n_in,
                              void* d_out, int out_size) {
    const float* dens  = (const float*)d_in[0];
    const float* pts   = (const float*)d_in[1];
    const int*   downp = (n_in >= 3) ? (const int*)d_in[2] : nullptr;
    float* out = (float*)d_out;

    k_zero<<<(TOTAL + 255) / 256, 256>>>(out);
    k_scatter<<<(BB * NPTS + 127) / 128, 128>>>(pts, downp);
    k_loss<<<(TOTAL + 255) / 256, 256>>>(dens, out);
}